// round 13
// baseline (speedup 1.0000x reference)
#include <cuda_runtime.h>
#include <math.h>

// ---------------------------------------------------------------------------
// Problem constants
// ---------------------------------------------------------------------------
#define BB      64      // batch
#define FRAMES  100
#define FF      193     // feature rows (last one = period)
#define NSUB    4
#define NT      512     // seq_kernel threads

// Packed transposed-weight offsets (layout (K, O), row k contiguous in o)
#define OFF_FW   0        // (388,64)   24832
#define OFF_FWG  24832    // (64,64)    4096
#define OFF_IH1  28928    // (128,192)  24576
#define OFF_HH1  53504    // (64,192)   12288
#define OFF_IH2  65792
#define OFF_HH2  90368
#define OFF_IH3  102656
#define OFF_HH3  127232
#define OFF_G1   139520   // (64,64)
#define OFF_G2   143616
#define OFF_G3   147712
#define OFF_SG   151808   // (128,128)  16384
#define OFF_SD   168192   // (320,128)  40960
#define OFF_OUT  209152   // (128,64)   8192
#define WT_TOTAL 217344

// ---------------------------------------------------------------------------
// Device scratch (allocation-free: __device__ globals)
// ---------------------------------------------------------------------------
__device__ __align__(16) float g_X [6400 * 256];
__device__ __align__(16) float g_H1[6400 * 256];
__device__ __align__(16) float g_H2[6400 * 256];
__device__ __align__(16) float g_C [6400 * 512];
__device__ __align__(16) float g_WT[WT_TOTAL];

// ---------------------------------------------------------------------------
// Accurate activations (expm1f is not fast-math-substituted; no cancellation).
// Known-good since R8 (rel_err 6.4e-7).
// ---------------------------------------------------------------------------
__device__ __forceinline__ float tanh_acc(float x) {
    float t  = fabsf(x);
    float em = expm1f(-2.0f * t);        // in (-1, 0]
    float r  = -em / (2.0f + em);        // tanh(t)
    return copysignf(r, x);
}

__device__ __forceinline__ float sig_acc(float x) {
    if (x >= 0.0f) {
        float em = expm1f(-x);
        return 1.0f / (2.0f + em);
    } else {
        float em = expm1f(x);
        return (1.0f + em) / (2.0f + em);
    }
}

// ---------------------------------------------------------------------------
// Partial-sum phases (no internal barriers). Weights in (K, O) layout.
// part512: all NT threads; writes P*O partials (P = NT/(O/4) -> P*O = 2048).
// part256: a 256-thread subgroup (t in [0,256)); P = 256/(O/4).
// ---------------------------------------------------------------------------
template<int O, int K>
__device__ __forceinline__ void part512(const float* __restrict__ W,
                                        const float* __restrict__ x,
                                        float* __restrict__ redb, int tid)
{
    constexpr int G = O / 4;
    constexpr int P = NT / G;
    const int g = tid % G;
    const int p = tid / G;
    float4 acc = make_float4(0.f, 0.f, 0.f, 0.f);
    for (int k = p; k < K; k += P) {
        float4 w = *reinterpret_cast<const float4*>(W + k * O + 4 * g);
        float xv = x[k];
        acc.x = fmaf(w.x, xv, acc.x);
        acc.y = fmaf(w.y, xv, acc.y);
        acc.z = fmaf(w.z, xv, acc.z);
        acc.w = fmaf(w.w, xv, acc.w);
    }
    *reinterpret_cast<float4*>(redb + p * O + 4 * g) = acc;
}

template<int O, int K>
__device__ __forceinline__ void part256(const float* __restrict__ W,
                                        const float* __restrict__ x,
                                        float* __restrict__ redb, int t)
{
    constexpr int G = O / 4;
    constexpr int P = 256 / G;
    const int g = t % G;
    const int p = t / G;
    if (p < P) {
        float4 acc = make_float4(0.f, 0.f, 0.f, 0.f);
        for (int k = p; k < K; k += P) {
            float4 w = *reinterpret_cast<const float4*>(W + k * O + 4 * g);
            float xv = x[k];
            acc.x = fmaf(w.x, xv, acc.x);
            acc.y = fmaf(w.y, xv, acc.y);
            acc.z = fmaf(w.z, xv, acc.z);
            acc.w = fmaf(w.w, xv, acc.w);
        }
        *reinterpret_cast<float4*>(redb + p * O + 4 * g) = acc;
    }
}

// ---------------------------------------------------------------------------
// Prep kernels (identical to R8)
// ---------------------------------------------------------------------------
__global__ void build_x_kernel(const float* __restrict__ features,
                               const float* __restrict__ gfeat)
{
    int r = blockIdx.x;            // r = b*FRAMES + t
    int tid = threadIdx.x;
    int b = r / FRAMES, t = r % FRAMES;
    float v;
    if (tid < 192) v = features[b * (FF * FRAMES) + tid * FRAMES + t];
    else           v = gfeat[b * 64 + (tid - 192)];
    g_X[r * 256 + tid] = v;
}

struct TPack { const float* src[14]; };

__global__ void transpose_all_kernel(TPack p)
{
    const int offs[14] = {OFF_FW, OFF_FWG, OFF_IH1, OFF_HH1, OFF_IH2, OFF_HH2,
                          OFF_IH3, OFF_HH3, OFF_G1, OFF_G2, OFF_G3, OFF_SG,
                          OFF_SD, OFF_OUT};
    const int Os[14]   = {64, 64, 192, 192, 192, 192, 192, 192,
                          64, 64, 64, 128, 128, 64};
    const int Ks[14]   = {388, 64, 128, 64, 128, 64, 128, 64,
                          64, 64, 64, 128, 320, 128};
    int m = blockIdx.y;
    int i = blockIdx.x * 256 + threadIdx.x;
    int O = Os[m], K = Ks[m];
    if (i < O * K) {
        int o = i / K, kk = i % K;
        g_WT[offs[m] + kk * O + o] = p.src[m][i];
    }
}

// Tiled GEMM with fused tanh: C[r,o] = tanh(sum_k A[r,k] * W[o,k]); K = 256.
__global__ void __launch_bounds__(256) gemm_tanh_kernel(
    const float* __restrict__ W, int mode)
{
    const float* A = (mode == 0) ? g_X : (mode == 1) ? g_H1 : g_H2;
    float* Cm      = (mode == 0) ? g_H1 : (mode == 1) ? g_H2 : g_C;
    const int K = 256;
    const int O = (mode == 2) ? 512 : 256;

    __shared__ __align__(16) float As[16][65];
    __shared__ __align__(16) float Ws[16][65];
    int tid = threadIdx.x;
    int tx = tid & 15, ty = tid >> 4;
    int r0 = blockIdx.x * 64, n0 = blockIdx.y * 64;
    int lm = tid >> 2, lk = (tid & 3) << 2;

    float acc[4][4];
    #pragma unroll
    for (int i = 0; i < 4; ++i)
        #pragma unroll
        for (int j = 0; j < 4; ++j) acc[i][j] = 0.f;

    for (int kk = 0; kk < K; kk += 16) {
        float4 a4 = *reinterpret_cast<const float4*>(A + (size_t)(r0 + lm) * K + kk + lk);
        float4 w4 = *reinterpret_cast<const float4*>(W + (size_t)(n0 + lm) * K + kk + lk);
        As[lk + 0][lm] = a4.x; As[lk + 1][lm] = a4.y;
        As[lk + 2][lm] = a4.z; As[lk + 3][lm] = a4.w;
        Ws[lk + 0][lm] = w4.x; Ws[lk + 1][lm] = w4.y;
        Ws[lk + 2][lm] = w4.z; Ws[lk + 3][lm] = w4.w;
        __syncthreads();
        #pragma unroll
        for (int kq = 0; kq < 16; ++kq) {
            float av[4], wv[4];
            #pragma unroll
            for (int i = 0; i < 4; ++i) av[i] = As[kq][ty * 4 + i];
            #pragma unroll
            for (int j = 0; j < 4; ++j) wv[j] = Ws[kq][tx * 4 + j];
            #pragma unroll
            for (int i = 0; i < 4; ++i)
                #pragma unroll
                for (int j = 0; j < 4; ++j)
                    acc[i][j] = fmaf(av[i], wv[j], acc[i][j]);
        }
        __syncthreads();
    }
    #pragma unroll
    for (int i = 0; i < 4; ++i)
        #pragma unroll
        for (int j = 0; j < 4; ++j)
            Cm[(size_t)(r0 + ty * 4 + i) * O + n0 + tx * 4 + j] = tanh_acc(acc[i][j]);
}

// ---------------------------------------------------------------------------
// Persistent sequential sampler: one CTA per batch element (64 CTAs),
// NT=512 threads, 400 serial steps, 23 barriers/step.
// prev[i] == ring[(head + i) & 511]. Wsd + Wout cached in 192 KB smem.
// Elementwise stages fused into reduction phases; gi/gh run concurrently.
// ---------------------------------------------------------------------------
__global__ void __launch_bounds__(NT, 1) seq_kernel(
    const float* __restrict__ features,
    const float* __restrict__ prev0,
    float* __restrict__ outg)
{
    extern __shared__ __align__(16) float dynsh[];
    float* WsdS  = dynsh;               // 40960 floats (160 KB)
    float* WoutS = dynsh + 40960;       //  8192 floats ( 32 KB)

    __shared__ __align__(16) float ring[512];
    __shared__ __align__(16) float s1[64], s2[64], s3[64], sfw[128];
    __shared__ __align__(16) float xbuf[388];
    __shared__ __align__(16) float fwpre[64], xg[128];
    __shared__ __align__(16) float skipb[320], sd[128], so[128];
    __shared__ __align__(16) float redf[2048];

    const int tid = threadIdx.x;
    const int b = blockIdx.x;

    for (int i = tid; i < 40960; i += NT) WsdS[i]  = g_WT[OFF_SD + i];
    for (int i = tid; i < 8192;  i += NT) WoutS[i] = g_WT[OFF_OUT + i];
    for (int i = tid; i < 512;   i += NT) ring[i]  = prev0[b * 512 + i];
    if (tid < 64)  { s1[tid] = 0.f; s2[tid] = 0.f; s3[tid] = 0.f; }
    if (tid < 128) sfw[tid] = 0.f;
    __syncthreads();

    int head = 0;
    for (int t = 0; t < FRAMES; ++t) {
        const int per = (int)rintf(features[b * (FF * FRAMES) + (FF - 1) * FRAMES + t]);
        const float* crow = g_C + (b * FRAMES + t) * 512;
        for (int k = 0; k < NSUB; ++k) {
            // ===== xbuf build: [feat2s(128)|prev_sub(64)|lookback(68)|sfw(128)]
            if (tid < 128) {
                xbuf[tid]       = crow[tid * 4 + k];
                xbuf[260 + tid] = sfw[tid];
            } else if (tid < 192) {
                int i = tid - 128;
                xbuf[tid] = ring[(head + 448 + i) & 511];
            }
            if (tid >= 188 && tid < 256) {          // lookback j = 0..67
                int j = tid - 188;
                int idx = 512 - per + j - 2;
                if (idx >= 512) idx -= per;
                xbuf[192 + j] = ring[(head + idx) & 511];
            }
            if (tid >= 256 && tid < 320)            // skipb[256:320] = prev_sub
                skipb[tid] = ring[(head + 448 + (tid - 256)) & 511];
            __syncthreads();                                           // (1)

            // ===== fw = glu(tanh(xbuf @ Wfw^T), Wfw_g)
            part512<64, 388>(g_WT + OFF_FW, xbuf, redf, tid);
            __syncthreads();                                           // (2)
            if (tid < 64) {
                float s = 0.f;
                #pragma unroll
                for (int q = 0; q < 32; ++q) s += redf[q * 64 + tid];
                fwpre[tid] = tanh_acc(s);
            }
            __syncthreads();                                           // (3)
            part512<64, 64>(g_WT + OFF_FWG, fwpre, redf, tid);
            __syncthreads();                                           // (4)
            if (tid < 64) {             // fused: reduce + GLU + xg setup
                float s = 0.f;
                #pragma unroll
                for (int q = 0; q < 32; ++q) s += redf[q * 64 + tid];
                float v = fwpre[tid] * sig_acc(s);
                skipb[192 + tid] = v;   // skip slot: fw
                xg[tid] = v;            // GRU1 input
            } else if (tid < 128) {
                xg[tid] = skipb[192 + tid];   // prev_sub half (skipb[256:320))
            }
            __syncthreads();                                           // (5)

            // ===== 3 x (GRU + GLU): gi||gh in one phase, gate fused in reduce
            #pragma unroll
            for (int l = 0; l < 3; ++l) {
                const float* WihT = g_WT + (l == 0 ? OFF_IH1 : l == 1 ? OFF_IH2 : OFF_IH3);
                const float* WhhT = g_WT + (l == 0 ? OFF_HH1 : l == 1 ? OFF_HH2 : OFF_HH3);
                const float* WgT  = g_WT + (l == 0 ? OFF_G1  : l == 1 ? OFF_G2  : OFF_G3);
                float* s = (l == 0 ? s1 : l == 1 ? s2 : s3);

                if (tid < 256) part256<192, 128>(WihT, xg, redf, tid);
                else           part256<192, 64 >(WhhT, s, redf + 1024, tid - 256);
                __syncthreads();                                       // (6,10,14)
                if (tid < 64) {         // fused: reduce gi+gh + GRU gate
                    float gi0 = 0.f, gi1 = 0.f, gi2 = 0.f;
                    float gh0 = 0.f, gh1 = 0.f, gh2 = 0.f;
                    #pragma unroll
                    for (int q = 0; q < 5; ++q) {
                        gi0 += redf[q * 192 + tid];
                        gi1 += redf[q * 192 + 64 + tid];
                        gi2 += redf[q * 192 + 128 + tid];
                        gh0 += redf[1024 + q * 192 + tid];
                        gh1 += redf[1024 + q * 192 + 64 + tid];
                        gh2 += redf[1024 + q * 192 + 128 + tid];
                    }
                    float r = sig_acc(gi0 + gh0);
                    float z = sig_acc(gi1 + gh1);
                    float n = tanh_acc(gi2 + r * gh2);
                    s[tid] = (1.0f - z) * n + z * s[tid];
                }
                __syncthreads();                                       // (7,11,15)
                part512<64, 64>(WgT, s, redf, tid);
                __syncthreads();                                       // (8,12,16)
                if (tid < 64) {         // fused: reduce + GLU
                    float acc = 0.f;
                    #pragma unroll
                    for (int q = 0; q < 32; ++q) acc += redf[q * 64 + tid];
                    float o = s[tid] * sig_acc(acc);
                    skipb[l * 64 + tid] = o;
                    xg[tid] = o;
                }
                __syncthreads();                                       // (9,13,17)
            }

            // ===== skip decoder + output
            part512<128, 320>(WsdS, skipb, redf, tid);
            __syncthreads();                                           // (18)
            if (tid < 128) {
                float s = 0.f;
                #pragma unroll
                for (int q = 0; q < 16; ++q) s += redf[q * 128 + tid];
                sd[tid] = tanh_acc(s);
            }
            __syncthreads();                                           // (19)
            part512<128, 128>(g_WT + OFF_SG, sd, redf, tid);
            __syncthreads();                                           // (20)
            if (tid < 128) {            // fused: reduce + GLU
                float s = 0.f;
                #pragma unroll
                for (int q = 0; q < 16; ++q) s += redf[q * 128 + tid];
                so[tid] = sd[tid] * sig_acc(s);
            }
            __syncthreads();                                           // (21)
            part512<64, 128>(WoutS, so, redf, tid);
            __syncthreads();                                           // (22)
            if (tid < 64) {             // fused: reduce + tanh + emit + ring
                float s = 0.f;
                #pragma unroll
                for (int q = 0; q < 32; ++q) s += redf[q * 64 + tid];
                float v = tanh_acc(s);
                outg[b * 25600 + t * 256 + k * 64 + tid] = v;
                ring[(head + tid) & 511] = v;   // overwrites oldest 64
            } else if (tid < 192) {
                sfw[tid - 64] = xbuf[tid - 64]; // new sfw = current feat2s
            }
            __syncthreads();                                           // (23)
            head = (head + 64) & 511;
        }
    }
}

// ---------------------------------------------------------------------------
// Host launcher (graph-capturable: kernel launches only)
// ---------------------------------------------------------------------------
extern "C" void kernel_launch(void* const* d_in, const int* in_sizes, int n_in,
                              void* d_out, int out_size)
{
    const float* features = (const float*)d_in[0];
    const float* gfeat    = (const float*)d_in[1];
    const float* prev     = (const float*)d_in[2];
    const float* Wc1      = (const float*)d_in[3];
    const float* Wc2      = (const float*)d_in[4];
    const float* Wc3      = (const float*)d_in[5];
    float* out = (float*)d_out;

    build_x_kernel<<<6400, 256>>>(features, gfeat);

    TPack tp;
    for (int i = 0; i < 14; ++i) tp.src[i] = (const float*)d_in[6 + i];
    transpose_all_kernel<<<dim3(160, 14), 256>>>(tp);

    gemm_tanh_kernel<<<dim3(100, 4), 256>>>(Wc1, 0);
    gemm_tanh_kernel<<<dim3(100, 4), 256>>>(Wc2, 1);
    gemm_tanh_kernel<<<dim3(100, 8), 256>>>(Wc3, 2);

    cudaFuncSetAttribute(seq_kernel,
                         cudaFuncAttributeMaxDynamicSharedMemorySize, 196608);
    seq_kernel<<<BB, NT, 196608>>>(features, prev, out);
}

// round 15
// speedup vs baseline: 1.3658x; 1.3658x over previous
#include <cuda_runtime.h>
#include <math.h>

// ---------------------------------------------------------------------------
// Problem constants
// ---------------------------------------------------------------------------
#define BB      64      // batch
#define FRAMES  100
#define FF      193     // feature rows (last one = period)
#define NSUB    4
#define NT      256     // seq_kernel threads (R8 structure)

// Packed transposed-weight offsets (layout (K, O), row k contiguous in o)
// OFF_FW now holds only the DYNAMIC fw columns: (132, 64) = 8448 floats.
#define OFF_FW   0        // (132,64)   8448   (dynamic cols 128..259 of Wfw)
#define OFF_FWG  24832    // (64,64)    4096
#define OFF_IH1  28928    // (128,192)  24576
#define OFF_HH1  53504    // (64,192)   12288
#define OFF_IH2  65792
#define OFF_HH2  90368
#define OFF_IH3  102656
#define OFF_HH3  127232
#define OFF_G1   139520   // (64,64)
#define OFF_G2   143616
#define OFF_G3   147712
#define OFF_SG   151808   // (128,128) 16384
#define OFF_SD   168192   // (320,128) 40960
#define OFF_OUT  209152   // (128,64)   8192
#define WT_TOTAL 217344

// ---------------------------------------------------------------------------
// Device scratch (allocation-free: __device__ globals)
// ---------------------------------------------------------------------------
__device__ __align__(16) float g_X  [6400 * 256];
__device__ __align__(16) float g_H1 [6400 * 256];
__device__ __align__(16) float g_H2 [6400 * 256];
__device__ __align__(16) float g_C  [6400 * 512];
__device__ __align__(16) float g_WT [WT_TOTAL];
__device__ __align__(16) float g_WS [64 * 256];       // static fw cols, (64,256)
__device__ __align__(16) float g_FS [25600 * 256];    // [feat2s|sfw] per subframe
__device__ __align__(16) float g_FWS[25600 * 64];     // precomputed static fw sums

// ---------------------------------------------------------------------------
// Fast overflow-safe activations (explicit __expf = MUFU.EX2 path, ~1e-7 rel
// error per call; R8 proved the recurrence is contractive: total rel_err
// 6.4e-7 with exact activations, threshold 1e-3).
// ---------------------------------------------------------------------------
__device__ __forceinline__ float tanh_f(float x) {
    float t = fminf(fabsf(x), 15.0f);
    float e = __expf(2.0f * t);          // finite
    float r = 1.0f - 2.0f / (e + 1.0f);  // tanh(t) >= 0, no cancellation
    return copysignf(r, x);
}

__device__ __forceinline__ float sig_f(float x) {
    float u = __expf(-fabsf(x));         // (0, 1]
    return (x >= 0.0f) ? 1.0f / (1.0f + u) : u / (1.0f + u);
}

// ---------------------------------------------------------------------------
// Block-cooperative matvec (256 threads): y[o] = act(bias[o] + sum_k W[k*O+o]*x[k])
// W in (K, O) layout; optional bias. Coalesced float4 weight loads.
// ---------------------------------------------------------------------------
template<int O, int K, int ACT>
__device__ __forceinline__ void mv(const float* __restrict__ W,
                                   const float* __restrict__ x,
                                   float* __restrict__ y,
                                   float* __restrict__ redf,
                                   int tid,
                                   const float* __restrict__ bias = nullptr)
{
    constexpr int G = O / 4;        // output groups of 4
    constexpr int P = 256 / G;      // k-split factor (16 / 8 / 5)
    const int g = tid % G;
    const int p = tid / G;
    float4 acc = make_float4(0.f, 0.f, 0.f, 0.f);
    if (p < P) {
        #pragma unroll
        for (int k = p; k < K; k += P) {
            float4 w = *reinterpret_cast<const float4*>(W + k * O + 4 * g);
            float xv = x[k];
            acc.x = fmaf(w.x, xv, acc.x);
            acc.y = fmaf(w.y, xv, acc.y);
            acc.z = fmaf(w.z, xv, acc.z);
            acc.w = fmaf(w.w, xv, acc.w);
        }
        *reinterpret_cast<float4*>(redf + p * O + 4 * g) = acc;
    }
    __syncthreads();
    if (tid < O) {
        float s = bias ? bias[tid] : 0.f;
        #pragma unroll
        for (int q = 0; q < P; ++q) s += redf[q * O + tid];
        y[tid] = ACT ? tanh_f(s) : s;
    }
    __syncthreads();
}

// GRU + GLU stage (R8 structure). xg = [input(64) | prev_sub(64)], s updated
// in place; GLU result to skipslot and chained into xg[0:64].
__device__ __forceinline__ void gru_glu(const float* WihT, const float* WhhT,
                                        const float* WgT,
                                        float* s, float* skipslot, float* xg,
                                        float* gi, float* gh, float* t64,
                                        float* redf, int tid)
{
    mv<192, 128, 0>(WihT, xg, gi, redf, tid);
    mv<192, 64, 0>(WhhT, s, gh, redf, tid);
    if (tid < 64) {
        float r = sig_f(gi[tid]        + gh[tid]);
        float z = sig_f(gi[64 + tid]   + gh[64 + tid]);
        float n = tanh_f(gi[128 + tid] + r * gh[128 + tid]);
        s[tid] = (1.0f - z) * n + z * s[tid];
    }
    __syncthreads();
    mv<64, 64, 0>(WgT, s, t64, redf, tid);
    if (tid < 64) {
        float o = s[tid] * sig_f(t64[tid]);
        skipslot[tid] = o;
        xg[tid] = o;
    }
    __syncthreads();
}

// ---------------------------------------------------------------------------
// Prep kernels
// ---------------------------------------------------------------------------
__global__ void build_x_kernel(const float* __restrict__ features,
                               const float* __restrict__ gfeat)
{
    int r = blockIdx.x;            // r = b*FRAMES + t
    int tid = threadIdx.x;
    int b = r / FRAMES, t = r % FRAMES;
    float v;
    if (tid < 192) v = features[b * (FF * FRAMES) + tid * FRAMES + t];
    else           v = gfeat[b * 64 + (tid - 192)];
    g_X[r * 256 + tid] = v;
}

// Transposes (with source column offset + row stride for the FW dynamic slice).
struct TPack { const float* src[14]; };

__global__ void transpose_all_kernel(TPack p)
{
    const int offs[14] = {OFF_FW, OFF_FWG, OFF_IH1, OFF_HH1, OFF_IH2, OFF_HH2,
                          OFF_IH3, OFF_HH3, OFF_G1, OFF_G2, OFF_G3, OFF_SG,
                          OFF_SD, OFF_OUT};
    const int Os[14]   = {64, 64, 192, 192, 192, 192, 192, 192,
                          64, 64, 64, 128, 128, 64};
    const int Ks[14]   = {132, 64, 128, 64, 128, 64, 128, 64,
                          64, 64, 64, 128, 320, 128};
    const int Ss[14]   = {388, 64, 128, 64, 128, 64, 128, 64,
                          64, 64, 64, 128, 320, 128};   // src row stride
    const int Cs[14]   = {128, 0, 0, 0, 0, 0, 0, 0,
                          0, 0, 0, 0, 0, 0};            // src col offset
    int m = blockIdx.y;
    int i = blockIdx.x * 256 + threadIdx.x;
    int O = Os[m], K = Ks[m];
    if (i < O * K) {
        int o = i / K, kk = i % K;
        g_WT[offs[m] + kk * O + o] = p.src[m][o * Ss[m] + Cs[m] + kk];
    }
}

// Static fw weight matrix: g_WS[o][j] = Wfw[o][ j<128 ? j : 132+j ]
// (cols [0,128) = feat2s, cols [260,388) = sfw)
__global__ void build_ws_kernel(const float* __restrict__ Wfw)
{
    int o = blockIdx.x, j = threadIdx.x;
    int i = (j < 128) ? j : 132 + j;
    g_WS[o * 256 + j] = Wfw[o * 388 + i];
}

// g_FS row per subframe (b,t,k): [feat2s(128) | sfw(128)], sfw = previous
// subframe's feat2s (zeros for t=0,k=0).
__global__ void build_fs_kernel()
{
    int r = blockIdx.x;                 // 0..25599
    int b = r / 400, rem = r % 400;
    int t = rem / 4, k = rem % 4;
    int j = threadIdx.x;
    float v;
    if (j < 128) {
        v = g_C[(b * 100 + t) * 512 + j * 4 + k];
    } else {
        int i = j - 128;
        if (t == 0 && k == 0) v = 0.f;
        else {
            int kp = k ? k - 1 : 3;
            int tp = k ? t : t - 1;
            v = g_C[(b * 100 + tp) * 512 + i * 4 + kp];
        }
    }
    g_FS[r * 256 + j] = v;
}

// Generic tiled GEMM, K=256: C[r,o] = act? tanh(sum) : sum. W is (O,256)
// row-major. Used for the 3 conv layers and the fw-static precompute.
__global__ void __launch_bounds__(256) gemm256_kernel(
    const float* __restrict__ A, const float* __restrict__ W,
    float* __restrict__ Cm, int O, int act)
{
    const int K = 256;
    __shared__ __align__(16) float As[16][65];
    __shared__ __align__(16) float Ws[16][65];
    int tid = threadIdx.x;
    int tx = tid & 15, ty = tid >> 4;
    int r0 = blockIdx.x * 64, n0 = blockIdx.y * 64;
    int lm = tid >> 2, lk = (tid & 3) << 2;

    float acc[4][4];
    #pragma unroll
    for (int i = 0; i < 4; ++i)
        #pragma unroll
        for (int j = 0; j < 4; ++j) acc[i][j] = 0.f;

    for (int kk = 0; kk < K; kk += 16) {
        float4 a4 = *reinterpret_cast<const float4*>(A + (size_t)(r0 + lm) * K + kk + lk);
        float4 w4 = *reinterpret_cast<const float4*>(W + (size_t)(n0 + lm) * K + kk + lk);
        As[lk + 0][lm] = a4.x; As[lk + 1][lm] = a4.y;
        As[lk + 2][lm] = a4.z; As[lk + 3][lm] = a4.w;
        Ws[lk + 0][lm] = w4.x; Ws[lk + 1][lm] = w4.y;
        Ws[lk + 2][lm] = w4.z; Ws[lk + 3][lm] = w4.w;
        __syncthreads();
        #pragma unroll
        for (int kq = 0; kq < 16; ++kq) {
            float av[4], wv[4];
            #pragma unroll
            for (int i = 0; i < 4; ++i) av[i] = As[kq][ty * 4 + i];
            #pragma unroll
            for (int j = 0; j < 4; ++j) wv[j] = Ws[kq][tx * 4 + j];
            #pragma unroll
            for (int i = 0; i < 4; ++i)
                #pragma unroll
                for (int j = 0; j < 4; ++j)
                    acc[i][j] = fmaf(av[i], wv[j], acc[i][j]);
        }
        __syncthreads();
    }
    #pragma unroll
    for (int i = 0; i < 4; ++i)
        #pragma unroll
        for (int j = 0; j < 4; ++j) {
            float v = acc[i][j];
            Cm[(size_t)(r0 + ty * 4 + i) * O + n0 + tx * 4 + j] = act ? tanh_f(v) : v;
        }
}

// ---------------------------------------------------------------------------
// Persistent sequential sampler: one CTA per batch element (64 CTAs),
// 256 threads, 400 serial steps. prev[i] == ring[(head + i) & 511].
// Wsd + Wout cached in 192 KB smem. fw static part precomputed (g_FWS);
// only the 132 dynamic inputs (prev_sub + lookback) hit Wfw in the loop.
// ---------------------------------------------------------------------------
__global__ void __launch_bounds__(NT, 1) seq_kernel(
    const float* __restrict__ features,
    const float* __restrict__ prev0,
    float* __restrict__ outg)
{
    extern __shared__ __align__(16) float dynsh[];
    float* WsdS  = dynsh;               // 40960 floats (160 KB)
    float* WoutS = dynsh + 40960;       //  8192 floats ( 32 KB)

    __shared__ __align__(16) float ring[512];
    __shared__ __align__(16) float s1[64], s2[64], s3[64];
    __shared__ __align__(16) float xd[136];            // [prev_sub(64)|lookback(68)]
    __shared__ __align__(16) float fwpre[64], t64[64], xg[128];
    __shared__ __align__(16) float gi[192], gh[192];
    __shared__ __align__(16) float skipb[320], sd[128], t128[128], so[128], outv[64];
    __shared__ __align__(16) float redf[1024];

    const int tid = threadIdx.x;
    const int b = blockIdx.x;

    for (int i = tid; i < 40960; i += NT) WsdS[i]  = g_WT[OFF_SD + i];
    for (int i = tid; i < 8192;  i += NT) WoutS[i] = g_WT[OFF_OUT + i];
    for (int i = tid; i < 512;   i += NT) ring[i]  = prev0[b * 512 + i];
    if (tid < 64) { s1[tid] = 0.f; s2[tid] = 0.f; s3[tid] = 0.f; }
    __syncthreads();

    int head = 0;
    for (int t = 0; t < FRAMES; ++t) {
        const int per = (int)rintf(features[b * (FF * FRAMES) + (FF - 1) * FRAMES + t]);
        for (int k = 0; k < NSUB; ++k) {
            const float* fwsrow = g_FWS + (size_t)(((b * 100 + t) * 4) + k) * 64;

            // -- build dynamic inputs: prev_sub + lookback
            if (tid < 64) {
                float v = ring[(head + 448 + tid) & 511];
                xd[tid] = v;
                skipb[256 + tid] = v;          // skip slot 4: prev_sub
            }
            if (tid >= 188) {                  // lookback j = 0..67
                int j = tid - 188;
                int idx = 512 - per + j - 2;
                if (idx >= 512) idx -= per;
                xd[64 + j] = ring[(head + idx) & 511];
            }
            __syncthreads();

            // -- fw = glu(tanh(static + Wfw_dyn·xd), Wfw_g)
            mv<64, 132, 1>(g_WT + OFF_FW, xd, fwpre, redf, tid, fwsrow);
            mv<64, 64, 0>(g_WT + OFF_FWG, fwpre, t64, redf, tid);
            if (tid < 64) {
                float v = fwpre[tid] * sig_f(t64[tid]);
                skipb[192 + tid] = v;   // skip slot: fw
                xg[tid] = v;            // GRU1 input
            }
            if (tid >= 64 && tid < 128) xg[tid] = skipb[192 + tid]; // prev_sub
            __syncthreads();

            // -- 3 x (GRU + GLU)
            gru_glu(g_WT + OFF_IH1, g_WT + OFF_HH1, g_WT + OFF_G1,
                    s1, skipb + 0,   xg, gi, gh, t64, redf, tid);
            gru_glu(g_WT + OFF_IH2, g_WT + OFF_HH2, g_WT + OFF_G2,
                    s2, skipb + 64,  xg, gi, gh, t64, redf, tid);
            gru_glu(g_WT + OFF_IH3, g_WT + OFF_HH3, g_WT + OFF_G3,
                    s3, skipb + 128, xg, gi, gh, t64, redf, tid);

            // -- skip decoder + output
            mv<128, 320, 1>(WsdS, skipb, sd, redf, tid);
            mv<128, 128, 0>(g_WT + OFF_SG, sd, t128, redf, tid);
            if (tid < 128) so[tid] = sd[tid] * sig_f(t128[tid]);
            __syncthreads();
            mv<64, 128, 1>(WoutS, so, outv, redf, tid);

            // -- emit + roll ring
            if (tid < 64) {
                float v = outv[tid];
                outg[b * 25600 + t * 256 + k * 64 + tid] = v;
                ring[(head + tid) & 511] = v;   // overwrites oldest 64
            }
            __syncthreads();
            head = (head + 64) & 511;
        }
    }
}

// ---------------------------------------------------------------------------
// Host launcher (graph-capturable: kernel launches only)
// ---------------------------------------------------------------------------
extern "C" void kernel_launch(void* const* d_in, const int* in_sizes, int n_in,
                              void* d_out, int out_size)
{
    const float* features = (const float*)d_in[0];
    const float* gfeat    = (const float*)d_in[1];
    const float* prev     = (const float*)d_in[2];
    const float* Wc1      = (const float*)d_in[3];
    const float* Wc2      = (const float*)d_in[4];
    const float* Wc3      = (const float*)d_in[5];
    const float* Wfw      = (const float*)d_in[6];
    float* out = (float*)d_out;

    build_x_kernel<<<6400, 256>>>(features, gfeat);

    TPack tp;
    for (int i = 0; i < 14; ++i) tp.src[i] = (const float*)d_in[6 + i];
    transpose_all_kernel<<<dim3(160, 14), 256>>>(tp);
    build_ws_kernel<<<64, 256>>>(Wfw);

    // conv stack: g_X -> g_H1 -> g_H2 -> g_C
    float *g_X_p, *g_H1_p, *g_H2_p, *g_C_p, *g_FS_p, *g_WS_p, *g_FWS_p;
    cudaGetSymbolAddress((void**)&g_X_p,  g_X);
    cudaGetSymbolAddress((void**)&g_H1_p, g_H1);
    cudaGetSymbolAddress((void**)&g_H2_p, g_H2);
    cudaGetSymbolAddress((void**)&g_C_p,  g_C);
    cudaGetSymbolAddress((void**)&g_FS_p, g_FS);
    cudaGetSymbolAddress((void**)&g_WS_p, g_WS);
    cudaGetSymbolAddress((void**)&g_FWS_p, g_FWS);

    gemm256_kernel<<<dim3(100, 4), 256>>>(g_X_p,  Wc1, g_H1_p, 256, 1);
    gemm256_kernel<<<dim3(100, 4), 256>>>(g_H1_p, Wc2, g_H2_p, 256, 1);
    gemm256_kernel<<<dim3(100, 8), 256>>>(g_H2_p, Wc3, g_C_p,  512, 1);

    // fw static precompute: g_FS = [feat2s|sfw] rows; g_FWS = g_FS @ g_WS^T
    build_fs_kernel<<<25600, 256>>>();
    gemm256_kernel<<<dim3(400, 1), 256>>>(g_FS_p, g_WS_p, g_FWS_p, 64, 0);

    cudaFuncSetAttribute(seq_kernel,
                         cudaFuncAttributeMaxDynamicSharedMemorySize, 196608);
    seq_kernel<<<BB, NT, 196608>>>(features, prev, out);
}